// round 2
// baseline (speedup 1.0000x reference)
#include <cuda_runtime.h>
#include <cstdint>

// Problem constants (fixed shapes for this problem)
#define NR   32768      // rows of z
#define DIM  256        // code dim
#define KC   8192       // codebook size
#define MT   128        // rows per CTA
#define NT   128        // codes per tile
#define KT   16         // k per SMEM stage
#define SSTR 132        // padded SMEM stride (floats) -> bank-conflict-free
#define STAGES_PER_TILE (DIM / KT)                 // 16
#define NSTAGES ((KC / NT) * STAGES_PER_TILE)      // 64 * 16 = 1024
#define NBLOCKS (NR / MT)                          // 256

__device__ float g_esq[KC];
__device__ float g_partial[NBLOCKS];

// Packed fp32x2 FMA (Blackwell): d = a*b + d, elementwise on 2 packed floats.
#define FFMA2(d, a, b) \
    asm("fma.rn.f32x2 %0, %1, %2, %0;" : "+l"(d) : "l"(a), "l"(b))

// Duplicate one float into both lanes of a 64-bit packed pair.
#define PACKDUP(dst, f) do { \
    unsigned _b = __float_as_uint(f); \
    asm("mov.b64 %0, {%1, %1};" : "=l"(dst) : "r"(_b)); \
} while (0)

// ---------------------------------------------------------------------------
// Kernel 1: per-code squared norms ||E_c||^2.
// ONE THREAD per code, strictly sequential  acc = acc + round(v*v)  in
// ascending k order — replicating XLA's minor-dim reduce (mul and add
// rounded separately; intrinsics block fma contraction / fast-math).
// ---------------------------------------------------------------------------
__global__ void esq_kernel(const float* __restrict__ cb) {
    int c = blockIdx.x * blockDim.x + threadIdx.x;
    if (c >= KC) return;
    const float4* p = (const float4*)(cb + (size_t)c * DIM);
    float acc = 0.f;
#pragma unroll
    for (int k4 = 0; k4 < DIM / 4; ++k4) {
        float4 v = p[k4];
        acc = __fadd_rn(acc, __fmul_rn(v.x, v.x));
        acc = __fadd_rn(acc, __fmul_rn(v.y, v.y));
        acc = __fadd_rn(acc, __fmul_rn(v.z, v.z));
        acc = __fadd_rn(acc, __fmul_rn(v.w, v.w));
    }
    g_esq[c] = acc;
}

// ---------------------------------------------------------------------------
// Kernel 2: fused distance GEMM + argmin + STE gather + per-block loss.
// Distances replicate the reference's rounding exactly:
//   dist = fl( fl(z_sq - 2*M) + e_sq ),  M = sequential ascending-k fp32 FMA.
// ---------------------------------------------------------------------------
__global__ __launch_bounds__(256, 2)
void vq_main_kernel(const float* __restrict__ z,
                    const float* __restrict__ cb,
                    float* __restrict__ out) {
    __shared__ __align__(16) float zs[2][KT][SSTR];  // z tile, K-major
    __shared__ __align__(16) float cs[2][KT][SSTR];  // code tile, K-major
    __shared__ float zsq_s[MT];
    __shared__ float rmin[MT];
    __shared__ int   ridx[MT];
    __shared__ float red[256];

    const int t    = threadIdx.x;
    const int tx   = t & 15;        // code sub-tile
    const int ty   = t >> 4;        // row sub-tile
    const int row0 = blockIdx.x * MT;

    if (t < MT) { rmin[t] = 3.4028235e38f; ridx[t] = 0; }

    // --- per-row ||z||^2, sequential order matching XLA's reduce ---
    if (t < MT) {
        const float4* zp = (const float4*)(z + (size_t)(row0 + t) * DIM);
        float acc = 0.f;
#pragma unroll
        for (int k4 = 0; k4 < DIM / 4; ++k4) {
            float4 v = zp[k4];
            acc = __fadd_rn(acc, __fmul_rn(v.x, v.x));
            acc = __fadd_rn(acc, __fmul_rn(v.y, v.y));
            acc = __fadd_rn(acc, __fmul_rn(v.z, v.z));
            acc = __fadd_rn(acc, __fmul_rn(v.w, v.w));
        }
        zsq_s[t] = acc;
    }
    __syncthreads();

    // staging role: each thread loads 8 floats (2 x float4) of one row/code
    const int srow = t >> 1;            // 0..127 : z-row / code within tile
    const int skh  = (t & 1) * 8;       // k offset within stage: 0 or 8

    const float* zrow = z + (size_t)(row0 + srow) * DIM + skh;

    // --- prefetch stage 0 into registers ---
    float4 rz0 = *(const float4*)(zrow + 0);
    float4 rz1 = *(const float4*)(zrow + 4);
    float4 rc0, rc1;
    {
        const float* cp = cb + (size_t)srow * DIM + skh;  // tile 0, ks 0
        rc0 = *(const float4*)(cp + 0);
        rc1 = *(const float4*)(cp + 4);
    }

    unsigned long long acc[8][4];  // 8 rows x 4 code-pairs (8 codes)
#pragma unroll
    for (int i = 0; i < 8; i++)
#pragma unroll
        for (int j = 0; j < 4; j++) acc[i][j] = 0ull;

    int p = 0;
    for (int s = 0; s < NSTAGES; ++s) {
        // store staged registers (transposed to K-major)
        zs[p][skh + 0][srow] = rz0.x;  zs[p][skh + 1][srow] = rz0.y;
        zs[p][skh + 2][srow] = rz0.z;  zs[p][skh + 3][srow] = rz0.w;
        zs[p][skh + 4][srow] = rz1.x;  zs[p][skh + 5][srow] = rz1.y;
        zs[p][skh + 6][srow] = rz1.z;  zs[p][skh + 7][srow] = rz1.w;
        cs[p][skh + 0][srow] = rc0.x;  cs[p][skh + 1][srow] = rc0.y;
        cs[p][skh + 2][srow] = rc0.z;  cs[p][skh + 3][srow] = rc0.w;
        cs[p][skh + 4][srow] = rc1.x;  cs[p][skh + 5][srow] = rc1.y;
        cs[p][skh + 6][srow] = rc1.z;  cs[p][skh + 7][srow] = rc1.w;
        __syncthreads();

        // prefetch next stage (global -> regs), overlapped with compute below
        if (s + 1 < NSTAGES) {
            const int ns    = s + 1;
            const int nks   = ns & (STAGES_PER_TILE - 1);
            const int ntile = ns >> 4;
            const float* zp = zrow + nks * KT;
            rz0 = *(const float4*)(zp + 0);
            rz1 = *(const float4*)(zp + 4);
            const float* cp = cb + (size_t)(ntile * NT + srow) * DIM + nks * KT + skh;
            rc0 = *(const float4*)(cp + 0);
            rc1 = *(const float4*)(cp + 4);
        }

        // compute this stage (k ascending -> global k order 0..255 ascending)
        const float* zbp = &zs[p][0][ty * 8];
        const float* cbp = &cs[p][0][tx * 8];
#pragma unroll
        for (int k = 0; k < KT; ++k) {
            float4 za = *(const float4*)(zbp + k * SSTR);
            float4 zb = *(const float4*)(zbp + k * SSTR + 4);
            ulonglong2 ca  = *(const ulonglong2*)(cbp + k * SSTR);
            ulonglong2 cb2 = *(const ulonglong2*)(cbp + k * SSTR + 4);
#define ROW_FMA(i, zf) do { unsigned long long zd_; PACKDUP(zd_, zf);     \
            FFMA2(acc[i][0], zd_, ca.x);  FFMA2(acc[i][1], zd_, ca.y);    \
            FFMA2(acc[i][2], zd_, cb2.x); FFMA2(acc[i][3], zd_, cb2.y); } while (0)
            ROW_FMA(0, za.x); ROW_FMA(1, za.y); ROW_FMA(2, za.z); ROW_FMA(3, za.w);
            ROW_FMA(4, zb.x); ROW_FMA(5, zb.y); ROW_FMA(6, zb.z); ROW_FMA(7, zb.w);
#undef ROW_FMA
        }

        // end of a code tile: argmin epilogue with reference-matching rounding
        if ((s & (STAGES_PER_TILE - 1)) == STAGES_PER_TILE - 1) {
            const int tile  = s >> 4;
            const int cbase = tile * NT + tx * 8;
            float4 e0 = *(const float4*)(g_esq + cbase);
            float4 e1 = *(const float4*)(g_esq + cbase + 4);
            float ev[8] = {e0.x, e0.y, e0.z, e0.w, e1.x, e1.y, e1.z, e1.w};
#pragma unroll
            for (int i = 0; i < 8; i++) {
                const float zq2 = zsq_s[ty * 8 + i];
                float bv = 3.4028235e38f; int bi = 0x7fffffff;
#pragma unroll
                for (int j = 0; j < 4; j++) {
                    float d0 = __uint_as_float((unsigned)(acc[i][j] & 0xffffffffull));
                    float d1 = __uint_as_float((unsigned)(acc[i][j] >> 32));
                    // dist = fl( fl(z_sq - 2*M) + e_sq )   (2*M exact)
                    float v0 = __fadd_rn(__fsub_rn(zq2, d0 + d0), ev[2 * j]);
                    float v1 = __fadd_rn(__fsub_rn(zq2, d1 + d1), ev[2 * j + 1]);
                    if (v0 < bv) { bv = v0; bi = cbase + 2 * j; }
                    if (v1 < bv) { bv = v1; bi = cbase + 2 * j + 1; }
                    acc[i][j] = 0ull;
                }
                // reduce across the 16 lanes sharing this row group
#pragma unroll
                for (int m = 8; m > 0; m >>= 1) {
                    float ov = __shfl_xor_sync(0xffffffffu, bv, m);
                    int   oi = __shfl_xor_sync(0xffffffffu, bi, m);
                    if (ov < bv || (ov == bv && oi < bi)) { bv = ov; bi = oi; }
                }
                if (tx == 0) {
                    int r = ty * 8 + i;
                    if (bv < rmin[r]) { rmin[r] = bv; ridx[r] = bi; }  // strict <: first index wins ties
                }
            }
        }
        __syncthreads();
        p ^= 1;
    }

    // --- gather z_q, STE output z + fl(z_q - z), loss partial (deterministic)
    float lsum = 0.f;
#pragma unroll 1
    for (int it = 0; it < (MT * (DIM / 4)) / 256; ++it) {   // 32 iters
        int idx = it * 256 + t;
        int r   = idx >> 6;
        int d4  = (idx & 63) * 4;
        int ci  = ridx[r];
        float4 cv = *(const float4*)(cb + (size_t)ci * DIM + d4);
        float4 zv = *(const float4*)(z + (size_t)(row0 + r) * DIM + d4);
        float a0 = __fsub_rn(cv.x, zv.x), a1 = __fsub_rn(cv.y, zv.y);
        float a2 = __fsub_rn(cv.z, zv.z), a3 = __fsub_rn(cv.w, zv.w);
        float4 ov;
        ov.x = __fadd_rn(zv.x, a0);
        ov.y = __fadd_rn(zv.y, a1);
        ov.z = __fadd_rn(zv.z, a2);
        ov.w = __fadd_rn(zv.w, a3);
        *(float4*)(out + (size_t)(row0 + r) * DIM + d4) = ov;
        lsum += a0 * a0 + a1 * a1 + a2 * a2 + a3 * a3;
    }
    red[t] = lsum;
    __syncthreads();
    for (int off = 128; off > 0; off >>= 1) {
        if (t < off) red[t] += red[t + off];
        __syncthreads();
    }
    if (t == 0) g_partial[blockIdx.x] = red[0];
}

// ---------------------------------------------------------------------------
// Kernel 3: final loss reduction.  loss = 0.25*m + m,  m = mean((z_q - z)^2)
// ---------------------------------------------------------------------------
__global__ void loss_kernel(float* __restrict__ out, int write_loss) {
    __shared__ float red[256];
    int t = threadIdx.x;
    red[t] = g_partial[t];   // NBLOCKS == 256
    __syncthreads();
    for (int off = 128; off > 0; off >>= 1) {
        if (t < off) red[t] += red[t + off];
        __syncthreads();
    }
    if (t == 0 && write_loss) {
        float m = red[0] / (float)((size_t)NR * DIM);
        out[(size_t)NR * DIM] = __fadd_rn(__fmul_rn(0.25f, m), m);
    }
}

// ---------------------------------------------------------------------------
extern "C" void kernel_launch(void* const* d_in, const int* in_sizes, int n_in,
                              void* d_out, int out_size) {
    const float* z  = (const float*)d_in[0];
    const float* cb = (const float*)d_in[1];
    // defensive: identify by element counts (z is NR*DIM, codebook KC*DIM)
    if (n_in >= 2 && in_sizes[0] == KC * DIM && in_sizes[1] == NR * DIM) {
        const float* tmp = z; z = cb; cb = tmp;
    }
    float* out = (float*)d_out;

    esq_kernel<<<KC / 256, 256>>>(cb);
    vq_main_kernel<<<NBLOCKS, 256>>>(z, cb, out);
    int write_loss = (out_size > NR * DIM) ? 1 : 0;
    loss_kernel<<<1, 256>>>(out, write_loss);
}

// round 3
// speedup vs baseline: 1.1126x; 1.1126x over previous
#include <cuda_runtime.h>
#include <cstdint>

// Problem constants (fixed shapes for this problem)
#define NR   32768      // rows of z
#define DIM  256        // code dim
#define KC   8192       // codebook size
#define MT   128        // rows per CTA
#define NT   128        // codes per tile
#define KT   32         // k per code SMEM stage
#define SSTR 132        // padded SMEM stride for code tile (floats)
#define ZSTR 128        // z tile row stride (floats)
#define STAGES_PER_TILE (DIM / KT)                 // 8
#define NSTAGES ((KC / NT) * STAGES_PER_TILE)      // 64 * 8 = 512
#define NBLOCKS (NR / MT)                          // 256

#define SMEM_BYTES ((DIM * ZSTR + 2 * KT * SSTR) * 4)   // 164,864 B

__device__ float g_esq[KC];
__device__ float g_partial[NBLOCKS];

// Packed fp32x2 FMA (Blackwell): d = a*b + d, elementwise on 2 packed floats.
#define FFMA2(d, a, b) \
    asm("fma.rn.f32x2 %0, %1, %2, %0;" : "+l"(d) : "l"(a), "l"(b))

// Duplicate one float into both lanes of a 64-bit packed pair.
#define PACKDUP(dst, f) do { \
    unsigned _b = __float_as_uint(f); \
    asm("mov.b64 %0, {%1, %1};" : "=l"(dst) : "r"(_b)); \
} while (0)

// ---------------------------------------------------------------------------
// Kernel 1: per-code squared norms ||E_c||^2.
// ONE THREAD per code, strictly sequential  acc = acc + round(v*v)  in
// ascending k order — replicating XLA's minor-dim reduce.
// ---------------------------------------------------------------------------
__global__ void esq_kernel(const float* __restrict__ cb) {
    int c = blockIdx.x * blockDim.x + threadIdx.x;
    if (c >= KC) return;
    const float4* p = (const float4*)(cb + (size_t)c * DIM);
    float acc = 0.f;
#pragma unroll
    for (int k4 = 0; k4 < DIM / 4; ++k4) {
        float4 v = p[k4];
        acc = __fadd_rn(acc, __fmul_rn(v.x, v.x));
        acc = __fadd_rn(acc, __fmul_rn(v.y, v.y));
        acc = __fadd_rn(acc, __fmul_rn(v.z, v.z));
        acc = __fadd_rn(acc, __fmul_rn(v.w, v.w));
    }
    g_esq[c] = acc;
}

// ---------------------------------------------------------------------------
// Kernel 2: fused distance GEMM + argmin + STE gather + per-block loss.
// z tile persisted in SMEM (K-major) for the whole CTA lifetime; only the
// code tile streams through a double buffer with ONE sync per stage.
// Distances replicate the reference's rounding exactly:
//   dist = fl( fl(z_sq - 2*M) + e_sq ),  M = sequential ascending-k fp32 FMA.
// ---------------------------------------------------------------------------
__global__ __launch_bounds__(256, 1)
void vq_main_kernel(const float* __restrict__ z,
                    const float* __restrict__ cb,
                    float* __restrict__ out) {
    extern __shared__ __align__(16) float smem_dyn[];
    float (*zs)[ZSTR]      = (float(*)[ZSTR])smem_dyn;                 // [256][128]
    float (*cs)[KT][SSTR]  = (float(*)[KT][SSTR])(smem_dyn + DIM * ZSTR); // [2][32][132]

    __shared__ float zsq_s[MT];
    __shared__ int   ridx[MT];
    __shared__ float red[256];

    const int t    = threadIdx.x;
    const int tx   = t & 15;        // code sub-tile
    const int ty   = t >> 4;        // row sub-tile
    const int row0 = blockIdx.x * MT;

    // staging role
    const int srow = t >> 1;             // 0..127 : z-row / code row within tile
    const int half = t & 1;

    // --- load z tile once into SMEM, K-major (transposed) ---
    {
        const int kb = half * 128;       // this thread covers k in [kb, kb+128)
        const float* zp = z + (size_t)(row0 + srow) * DIM + kb;
#pragma unroll
        for (int k4 = 0; k4 < 32; ++k4) {
            float4 v = *(const float4*)(zp + k4 * 4);
            zs[kb + k4 * 4 + 0][srow] = v.x;
            zs[kb + k4 * 4 + 1][srow] = v.y;
            zs[kb + k4 * 4 + 2][srow] = v.z;
            zs[kb + k4 * 4 + 3][srow] = v.w;
        }
    }

    // --- per-row ||z||^2, sequential order matching XLA's reduce ---
    if (t < MT) {
        const float4* zp = (const float4*)(z + (size_t)(row0 + t) * DIM);
        float acc = 0.f;
#pragma unroll
        for (int k4 = 0; k4 < DIM / 4; ++k4) {
            float4 v = zp[k4];
            acc = __fadd_rn(acc, __fmul_rn(v.x, v.x));
            acc = __fadd_rn(acc, __fmul_rn(v.y, v.y));
            acc = __fadd_rn(acc, __fmul_rn(v.z, v.z));
            acc = __fadd_rn(acc, __fmul_rn(v.w, v.w));
        }
        zsq_s[t] = acc;
    }

    // --- prefetch code stage 0 into registers and store to buffer 0 ---
    const int skh = half * 16;           // k offset within stage: 0 or 16
    float4 rc0, rc1, rc2, rc3;
    {
        const float* cp = cb + (size_t)srow * DIM + skh;   // tile 0, stage 0
        rc0 = *(const float4*)(cp + 0);
        rc1 = *(const float4*)(cp + 4);
        rc2 = *(const float4*)(cp + 8);
        rc3 = *(const float4*)(cp + 12);
    }
#define STS_STAGE(buf) do {                                                  \
        cs[buf][skh +  0][srow] = rc0.x;  cs[buf][skh +  1][srow] = rc0.y;   \
        cs[buf][skh +  2][srow] = rc0.z;  cs[buf][skh +  3][srow] = rc0.w;   \
        cs[buf][skh +  4][srow] = rc1.x;  cs[buf][skh +  5][srow] = rc1.y;   \
        cs[buf][skh +  6][srow] = rc1.z;  cs[buf][skh +  7][srow] = rc1.w;   \
        cs[buf][skh +  8][srow] = rc2.x;  cs[buf][skh +  9][srow] = rc2.y;   \
        cs[buf][skh + 10][srow] = rc2.z;  cs[buf][skh + 11][srow] = rc2.w;   \
        cs[buf][skh + 12][srow] = rc3.x;  cs[buf][skh + 13][srow] = rc3.y;   \
        cs[buf][skh + 14][srow] = rc3.z;  cs[buf][skh + 15][srow] = rc3.w;   \
    } while (0)
    STS_STAGE(0);
    __syncthreads();

    unsigned long long acc[8][4];  // 8 rows x 4 code-pairs (8 codes)
#pragma unroll
    for (int i = 0; i < 8; i++)
#pragma unroll
        for (int j = 0; j < 4; j++) acc[i][j] = 0ull;

    // per-thread running argmin for the 8 rows this thread group owns
    float bvr[8];
    int   bir[8];
#pragma unroll
    for (int i = 0; i < 8; i++) { bvr[i] = 3.4028235e38f; bir[i] = 0; }

    int p = 0;
    for (int s = 0; s < NSTAGES; ++s) {
        // prefetch next code stage (global -> regs); overlaps with compute
        const bool has_next = (s + 1 < NSTAGES);
        if (has_next) {
            const int ns    = s + 1;
            const int nks   = ns & (STAGES_PER_TILE - 1);
            const int ntile = ns >> 3;
            const float* cp = cb + (size_t)(ntile * NT + srow) * DIM + nks * KT + skh;
            rc0 = *(const float4*)(cp + 0);
            rc1 = *(const float4*)(cp + 4);
            rc2 = *(const float4*)(cp + 8);
            rc3 = *(const float4*)(cp + 12);
        }

        // compute this stage (k ascending -> global k order 0..255 ascending)
        const int kbase = (s & (STAGES_PER_TILE - 1)) * KT;
        const float* cbp = &cs[p][0][tx * 8];
#pragma unroll
        for (int k = 0; k < KT; ++k) {
            float4 za = *(const float4*)(&zs[kbase + k][ty * 8]);
            float4 zb = *(const float4*)(&zs[kbase + k][ty * 8 + 4]);
            ulonglong2 ca  = *(const ulonglong2*)(cbp + k * SSTR);
            ulonglong2 cb2 = *(const ulonglong2*)(cbp + k * SSTR + 4);
#define ROW_FMA(i, zf) do { unsigned long long zd_; PACKDUP(zd_, zf);     \
            FFMA2(acc[i][0], zd_, ca.x);  FFMA2(acc[i][1], zd_, ca.y);    \
            FFMA2(acc[i][2], zd_, cb2.x); FFMA2(acc[i][3], zd_, cb2.y); } while (0)
            ROW_FMA(0, za.x); ROW_FMA(1, za.y); ROW_FMA(2, za.z); ROW_FMA(3, za.w);
            ROW_FMA(4, zb.x); ROW_FMA(5, zb.y); ROW_FMA(6, zb.z); ROW_FMA(7, zb.w);
#undef ROW_FMA
        }

        // end of a code tile: argmin epilogue with reference-matching rounding
        if ((s & (STAGES_PER_TILE - 1)) == STAGES_PER_TILE - 1) {
            const int tile  = s >> 3;
            const int cbase = tile * NT + tx * 8;
            float4 e0 = *(const float4*)(g_esq + cbase);
            float4 e1 = *(const float4*)(g_esq + cbase + 4);
            float ev[8] = {e0.x, e0.y, e0.z, e0.w, e1.x, e1.y, e1.z, e1.w};
#pragma unroll
            for (int i = 0; i < 8; i++) {
                const float zq2 = zsq_s[ty * 8 + i];
                float bv = 3.4028235e38f; int bi = 0x7fffffff;
#pragma unroll
                for (int j = 0; j < 4; j++) {
                    float d0 = __uint_as_float((unsigned)(acc[i][j] & 0xffffffffull));
                    float d1 = __uint_as_float((unsigned)(acc[i][j] >> 32));
                    // dist = fl( fl(z_sq - 2*M) + e_sq )   (2*M exact)
                    float v0 = __fadd_rn(__fsub_rn(zq2, d0 + d0), ev[2 * j]);
                    float v1 = __fadd_rn(__fsub_rn(zq2, d1 + d1), ev[2 * j + 1]);
                    if (v0 < bv) { bv = v0; bi = cbase + 2 * j; }
                    if (v1 < bv) { bv = v1; bi = cbase + 2 * j + 1; }
                    acc[i][j] = 0ull;
                }
                // reduce across the 16 lanes sharing this row group
#pragma unroll
                for (int m = 8; m > 0; m >>= 1) {
                    float ov = __shfl_xor_sync(0xffffffffu, bv, m);
                    int   oi = __shfl_xor_sync(0xffffffffu, bi, m);
                    if (ov < bv || (ov == bv && oi < bi)) { bv = ov; bi = oi; }
                }
                // first-index-wins across tiles (tiles visited in ascending order)
                if (bv < bvr[i]) { bvr[i] = bv; bir[i] = bi; }
            }
        }

        // store the prefetched stage into the other buffer, single sync
        if (has_next) {
            STS_STAGE(p ^ 1);
        }
        __syncthreads();
        p ^= 1;
    }

    if (tx == 0) {
#pragma unroll
        for (int i = 0; i < 8; i++) ridx[ty * 8 + i] = bir[i];
    }
    __syncthreads();

    // --- gather z_q, STE output z + fl(z_q - z), loss partial (deterministic)
    float lsum = 0.f;
#pragma unroll 1
    for (int it = 0; it < (MT * (DIM / 4)) / 256; ++it) {   // 32 iters
        int idx = it * 256 + t;
        int r   = idx >> 6;
        int d4  = (idx & 63) * 4;
        int ci  = ridx[r];
        float4 cv = *(const float4*)(cb + (size_t)ci * DIM + d4);
        float4 zv = *(const float4*)(z + (size_t)(row0 + r) * DIM + d4);
        float a0 = __fsub_rn(cv.x, zv.x), a1 = __fsub_rn(cv.y, zv.y);
        float a2 = __fsub_rn(cv.z, zv.z), a3 = __fsub_rn(cv.w, zv.w);
        float4 ov;
        ov.x = __fadd_rn(zv.x, a0);
        ov.y = __fadd_rn(zv.y, a1);
        ov.z = __fadd_rn(zv.z, a2);
        ov.w = __fadd_rn(zv.w, a3);
        *(float4*)(out + (size_t)(row0 + r) * DIM + d4) = ov;
        lsum += a0 * a0 + a1 * a1 + a2 * a2 + a3 * a3;
    }
    red[t] = lsum;
    __syncthreads();
    for (int off = 128; off > 0; off >>= 1) {
        if (t < off) red[t] += red[t + off];
        __syncthreads();
    }
    if (t == 0) g_partial[blockIdx.x] = red[0];
}

// ---------------------------------------------------------------------------
// Kernel 3: final loss reduction.  loss = 0.25*m + m,  m = mean((z_q - z)^2)
// ---------------------------------------------------------------------------
__global__ void loss_kernel(float* __restrict__ out, int write_loss) {
    __shared__ float red[256];
    int t = threadIdx.x;
    red[t] = g_partial[t];   // NBLOCKS == 256
    __syncthreads();
    for (int off = 128; off > 0; off >>= 1) {
        if (t < off) red[t] += red[t + off];
        __syncthreads();
    }
    if (t == 0 && write_loss) {
        float m = red[0] / (float)((size_t)NR * DIM);
        out[(size_t)NR * DIM] = __fadd_rn(__fmul_rn(0.25f, m), m);
    }
}

// ---------------------------------------------------------------------------
extern "C" void kernel_launch(void* const* d_in, const int* in_sizes, int n_in,
                              void* d_out, int out_size) {
    const float* z  = (const float*)d_in[0];
    const float* cb = (const float*)d_in[1];
    // defensive: identify by element counts (z is NR*DIM, codebook KC*DIM)
    if (n_in >= 2 && in_sizes[0] == KC * DIM && in_sizes[1] == NR * DIM) {
        const float* tmp = z; z = cb; cb = tmp;
    }
    float* out = (float*)d_out;

    cudaFuncSetAttribute(vq_main_kernel,
                         cudaFuncAttributeMaxDynamicSharedMemorySize, SMEM_BYTES);

    esq_kernel<<<KC / 256, 256>>>(cb);
    vq_main_kernel<<<NBLOCKS, 256, SMEM_BYTES>>>(z, cb, out);
    int write_loss = (out_size > NR * DIM) ? 1 : 0;
    loss_kernel<<<1, 256>>>(out, write_loss);
}